// round 5
// baseline (speedup 1.0000x reference)
#include <cuda_runtime.h>
#include <cstdint>

// DCNv2 (modulated deformable conv), fused bilinear-sample + implicit GEMM.
// B=8, C=128, O=128, H=W=64, K=3, dilation=1, pad=1, dg=1.
// One CTA = one output image row (b, h fixed, 64 pixels). 256 threads.
// K-dim (C*9=1152) processed in 16 chunks of 72 (8 channels x 9 taps).
// Inner GEMM uses packed fma.rn.f32x2 (2 fp32 FMA/instr) for 2x FMA-pipe rate.

#define BB 8
#define CC 128
#define OO 128
#define HH 64
#define WW 64
#define KK 9
#define HW 4096
#define CHUNK_C 8
#define CHUNK_K 72            // CHUNK_C * 9
#define NCHUNK 16             // CC / CHUNK_C
#define TILE_P 64
#define NTHREADS 256

// smem layout (floats):
//   w_smem : [128][72]  = 9216
//   s_smem : [72][64]   = 4608
//   tap_i  : 576 int4   = 2304 (ints)
//   tap_w  : 576 float4 = 2304
#define W_OFF   0
#define S_OFF   9216
#define TI_OFF  13824
#define TW_OFF  16128
#define SMEM_FLOATS 18432
#define SMEM_BYTES  (SMEM_FLOATS * 4)

__device__ __forceinline__ unsigned long long pk2(float v) {
    unsigned long long r;
    asm("mov.b64 %0, {%1, %1};" : "=l"(r) : "f"(v));
    return r;
}
__device__ __forceinline__ void fma2(unsigned long long& d,
                                     unsigned long long a,
                                     unsigned long long b) {
    asm("fma.rn.f32x2 %0, %1, %2, %0;" : "+l"(d) : "l"(a), "l"(b));
}
__device__ __forceinline__ float2 u2f2(unsigned long long v) {
    float2 f;
    asm("mov.b64 {%0, %1}, %2;" : "=f"(f.x), "=f"(f.y) : "l"(v));
    return f;
}

__global__ void __launch_bounds__(NTHREADS, 2)
dcn_v2_kernel(const float* __restrict__ x,
              const float* __restrict__ offsets,
              const float* __restrict__ mask,
              const float* __restrict__ weight,
              const float* __restrict__ bias,
              float* __restrict__ out) {
    extern __shared__ float smem[];
    float*  w_smem = smem + W_OFF;
    float*  s_smem = smem + S_OFF;
    int4*   tap_i  = (int4*)(smem + TI_OFF);
    float4* tap_w  = (float4*)(smem + TW_OFF);

    const int tid = threadIdx.x;
    const int bIdx = blockIdx.x >> 6;     // image in batch
    const int h    = blockIdx.x & 63;     // output row

    // ---------------- per-(pixel,tap) bilinear precompute ----------------
    // 576 = 9 taps * 64 pixels
    for (int e = tid; e < KK * TILE_P; e += NTHREADS) {
        const int p = e & 63;
        const int t = e >> 6;             // 0..8
        const int ky = t / 3;
        const int kx = t - ky * 3;
        const int hw = (h << 6) + p;

        const size_t ob = ((size_t)bIdx * 18) << 12;
        const float dy = offsets[ob + ((size_t)(2 * t) << 12) + hw];
        const float dx = offsets[ob + ((size_t)(2 * t + 1) << 12) + hw];
        const float m  = mask[(((size_t)bIdx * 9 + t) << 12) + hw];

        const float py = (float)(h - 1 + ky) + dy;
        const float px = (float)(p - 1 + kx) + dx;
        const float fy = floorf(py);
        const float fx = floorf(px);
        const float ay = py - fy;         // wy1
        const float ax = px - fx;         // wx1
        const float by = 1.f - ay;        // wy0
        const float bx = 1.f - ax;        // wx0

        const float fy1 = fy + 1.f;
        const float fx1 = fx + 1.f;
        const bool vy0 = (fy  >= 0.f) && (fy  <= 63.f);
        const bool vy1 = (fy1 >= 0.f) && (fy1 <= 63.f);
        const bool vx0 = (fx  >= 0.f) && (fx  <= 63.f);
        const bool vx1 = (fx1 >= 0.f) && (fx1 <= 63.f);

        const int y0 = (int)fminf(fmaxf(fy,  0.f), 63.f);
        const int y1 = (int)fminf(fmaxf(fy1, 0.f), 63.f);
        const int x0 = (int)fminf(fmaxf(fx,  0.f), 63.f);
        const int x1 = (int)fminf(fmaxf(fx1, 0.f), 63.f);

        int4 ii;
        ii.x = (y0 << 6) + x0;
        ii.y = (y0 << 6) + x1;
        ii.z = (y1 << 6) + x0;
        ii.w = (y1 << 6) + x1;
        float4 ww;
        ww.x = (vy0 && vx0) ? by * bx * m : 0.f;
        ww.y = (vy0 && vx1) ? by * ax * m : 0.f;
        ww.z = (vy1 && vx0) ? ay * bx * m : 0.f;
        ww.w = (vy1 && vx1) ? ay * ax * m : 0.f;

        tap_i[e] = ii;   // layout [t][p] == linear e
        tap_w[e] = ww;
    }
    __syncthreads();

    // ---------------- register tile: 8 outputs x 4 pixels per thread -----
    const int ob8 = (tid >> 4) * 8;   // output base (16 groups of 8)
    const int pb4 = (tid & 15) * 4;   // pixel base  (16 groups of 4)

    unsigned long long acc[8][2];
#pragma unroll
    for (int i = 0; i < 8; ++i) { acc[i][0] = 0ull; acc[i][1] = 0ull; }

    const float* xp = x + ((size_t)bIdx << 19);  // b * C * HW

    for (int chunk = 0; chunk < NCHUNK; ++chunk) {
        const int c0 = chunk * CHUNK_C;
        if (chunk) __syncthreads();   // prior compute done reading smem

        // -- stage weight tile: w_smem[o][k] = weight[o][c0*9 + k], k in [0,72)
        {
            const float* wb = weight + c0 * 9;
#pragma unroll
            for (int i = tid; i < OO * CHUNK_K; i += NTHREADS) {
                const int o = i / CHUNK_K;
                const int k = i - o * CHUNK_K;
                w_smem[i] = __ldg(wb + (size_t)o * (CC * 9) + k);
            }
        }

        // -- build sampled tile: s_smem[k][p], k = cl*9 + t
#pragma unroll
        for (int v = tid; v < CHUNK_K * TILE_P; v += NTHREADS) {
            const int p  = v & 63;
            const int tk = v >> 6;        // 0..71
            const int cl = tk / 9;
            const int t  = tk - cl * 9;
            const int4   ii = tap_i[(t << 6) + p];
            const float4 ww = tap_w[(t << 6) + p];
            const float* pl = xp + ((size_t)(c0 + cl) << 12);
            const float val = ww.x * __ldg(pl + ii.x)
                            + ww.y * __ldg(pl + ii.y)
                            + ww.z * __ldg(pl + ii.z)
                            + ww.w * __ldg(pl + ii.w);
            s_smem[v] = val;
        }
        __syncthreads();

        // -- accumulate: acc[o][pix-pair] += w[o][k] * s[k][pix]
#pragma unroll
        for (int k4 = 0; k4 < CHUNK_K / 4; ++k4) {
            const int k = k4 * 4;
            const ulonglong2 s0 = *(const ulonglong2*)(s_smem + (k + 0) * 64 + pb4);
            const ulonglong2 s1 = *(const ulonglong2*)(s_smem + (k + 1) * 64 + pb4);
            const ulonglong2 s2 = *(const ulonglong2*)(s_smem + (k + 2) * 64 + pb4);
            const ulonglong2 s3 = *(const ulonglong2*)(s_smem + (k + 3) * 64 + pb4);
#pragma unroll
            for (int i = 0; i < 8; ++i) {
                const float4 wv = *(const float4*)(w_smem + (ob8 + i) * CHUNK_K + k);
                const unsigned long long w0 = pk2(wv.x);
                const unsigned long long w1 = pk2(wv.y);
                const unsigned long long w2 = pk2(wv.z);
                const unsigned long long w3 = pk2(wv.w);
                fma2(acc[i][0], w0, s0.x); fma2(acc[i][1], w0, s0.y);
                fma2(acc[i][0], w1, s1.x); fma2(acc[i][1], w1, s1.y);
                fma2(acc[i][0], w2, s2.x); fma2(acc[i][1], w2, s2.y);
                fma2(acc[i][0], w3, s3.x); fma2(acc[i][1], w3, s3.y);
            }
        }
    }

    // ---------------- epilogue: + bias, store float4 ---------------------
#pragma unroll
    for (int i = 0; i < 8; ++i) {
        const int o = ob8 + i;
        const float bi = __ldg(bias + o);
        const float2 v0 = u2f2(acc[i][0]);
        const float2 v1 = u2f2(acc[i][1]);
        float4 r;
        r.x = v0.x + bi;
        r.y = v0.y + bi;
        r.z = v1.x + bi;
        r.w = v1.y + bi;
        float* po = out + (((size_t)bIdx * OO + o) << 12) + (h << 6) + pb4;
        *(float4*)po = r;
    }
}

extern "C" void kernel_launch(void* const* d_in, const int* in_sizes, int n_in,
                              void* d_out, int out_size) {
    const float* x       = (const float*)d_in[0];
    const float* offsets = (const float*)d_in[1];
    const float* mask    = (const float*)d_in[2];
    const float* weight  = (const float*)d_in[3];
    const float* bias    = (const float*)d_in[4];
    float* out = (float*)d_out;

    cudaFuncSetAttribute(dcn_v2_kernel,
                         cudaFuncAttributeMaxDynamicSharedMemorySize, SMEM_BYTES);

    dcn_v2_kernel<<<BB * HH, NTHREADS, SMEM_BYTES>>>(x, offsets, mask, weight, bias, out);
}

// round 6
// speedup vs baseline: 1.0363x; 1.0363x over previous
#include <cuda_runtime.h>
#include <cstdint>

// DCNv2 fused bilinear-sample + implicit GEMM, software-pipelined.
// B=8, C=O=128, H=W=64, K=3, pad=dilation=1, dg=1.
// One CTA = one output image row (64 pixels), 256 threads, 2 CTAs/SM.
// K-dim (1152) in 16 chunks of 72 (8 ch x 9 taps).
// Double-buffered s & w smem tiles; taps live in registers; one sync/chunk.
// Inner GEMM: packed fma.rn.f32x2 (2 fp32 FMA / instr).

#define BB 8
#define CC 128
#define OO 128
#define HW 4096
#define CHUNK_C 8
#define CHUNK_K 72
#define NCHUNK 16
#define NTHREADS 256

// smem floats: w[2][128*72] = 2*9216, s[2][72*64] = 2*4608
#define SMEM_FLOATS (2 * 9216 + 2 * 4608)
#define SMEM_BYTES (SMEM_FLOATS * 4)

__device__ __forceinline__ unsigned long long pk2(float v) {
    unsigned long long r;
    asm("mov.b64 %0, {%1, %1};" : "=l"(r) : "f"(v));
    return r;
}
__device__ __forceinline__ void fma2(unsigned long long& d,
                                     unsigned long long a,
                                     unsigned long long b) {
    asm("fma.rn.f32x2 %0, %1, %2, %0;" : "+l"(d) : "l"(a), "l"(b));
}
__device__ __forceinline__ float2 u2f2(unsigned long long v) {
    float2 f;
    asm("mov.b64 {%0, %1}, %2;" : "=f"(f.x), "=f"(f.y) : "l"(v));
    return f;
}

// Stage weight tile for chunk starting at channel c0 into wbuf[128][72].
__device__ __forceinline__ void stage_w(const float* __restrict__ weight,
                                        float4* __restrict__ dst,
                                        int c0, int tid) {
#pragma unroll
    for (int it = 0; it < 9; ++it) {
        const int idx = tid + it * NTHREADS;   // 0..2303
        const int o = idx / 18;
        const int k4 = idx - o * 18;
        dst[idx] = __ldg((const float4*)(weight + (size_t)o * (CC * 9) + c0 * 9) + k4);
    }
}

__global__ void __launch_bounds__(NTHREADS, 2)
dcn_v2_kernel(const float* __restrict__ x,
              const float* __restrict__ offsets,
              const float* __restrict__ mask,
              const float* __restrict__ weight,
              const float* __restrict__ bias,
              float* __restrict__ out) {
    extern __shared__ float smem[];
    float* wbuf[2] = { smem,          smem + 9216 };
    float* sbuf[2] = { smem + 18432,  smem + 23040 };

    const int tid  = threadIdx.x;
    const int bIdx = blockIdx.x >> 6;
    const int h    = blockIdx.x & 63;
    const float* xp = x + ((size_t)bIdx << 19);

    // ---------------- register-resident bilinear taps --------------------
    // 576 taps (9 per pixel x 64 pixels); thread owns e = tid + 256*j.
    const int ntaps = (tid < 64) ? 3 : 2;
    uint2  tio[3];   // packed corner element indices: (i0 | i1<<16), (i2 | i3<<16)
    float4 twt[3];   // mask-folded corner weights
    int    tsb[3];   // s-tile base offset: t*64 + p

#pragma unroll
    for (int j = 0; j < 3; ++j) {
        tio[j] = make_uint2(0u, 0u);
        twt[j] = make_float4(0.f, 0.f, 0.f, 0.f);
        tsb[j] = 0;
        if (j < ntaps) {
            const int e = tid + (j << 8);
            const int t = e >> 6;
            const int p = e & 63;
            const int ky = t / 3;
            const int kx = t - ky * 3;
            const int hw = (h << 6) + p;

            const size_t ob = ((size_t)bIdx * 18) << 12;
            const float dy = offsets[ob + ((size_t)(2 * t) << 12) + hw];
            const float dx = offsets[ob + ((size_t)(2 * t + 1) << 12) + hw];
            const float m  = mask[(((size_t)bIdx * 9 + t) << 12) + hw];

            const float py = (float)(h - 1 + ky) + dy;
            const float px = (float)(p - 1 + kx) + dx;
            const float fy = floorf(py);
            const float fx = floorf(px);
            const float ay = py - fy;
            const float ax = px - fx;
            const float by = 1.f - ay;
            const float bx = 1.f - ax;

            const float fy1 = fy + 1.f;
            const float fx1 = fx + 1.f;
            const bool vy0 = (fy  >= 0.f) && (fy  <= 63.f);
            const bool vy1 = (fy1 >= 0.f) && (fy1 <= 63.f);
            const bool vx0 = (fx  >= 0.f) && (fx  <= 63.f);
            const bool vx1 = (fx1 >= 0.f) && (fx1 <= 63.f);

            const int y0 = (int)fminf(fmaxf(fy,  0.f), 63.f);
            const int y1 = (int)fminf(fmaxf(fy1, 0.f), 63.f);
            const int x0 = (int)fminf(fmaxf(fx,  0.f), 63.f);
            const int x1 = (int)fminf(fmaxf(fx1, 0.f), 63.f);

            const unsigned i0 = (unsigned)((y0 << 6) + x0);
            const unsigned i1 = (unsigned)((y0 << 6) + x1);
            const unsigned i2 = (unsigned)((y1 << 6) + x0);
            const unsigned i3 = (unsigned)((y1 << 6) + x1);
            tio[j] = make_uint2(i0 | (i1 << 16), i2 | (i3 << 16));
            twt[j] = make_float4((vy0 && vx0) ? by * bx * m : 0.f,
                                 (vy0 && vx1) ? by * ax * m : 0.f,
                                 (vy1 && vx0) ? ay * bx * m : 0.f,
                                 (vy1 && vx1) ? ay * ax * m : 0.f);
            tsb[j] = (t << 6) + p;
        }
    }

    // ---------------- register tile: 8 outputs x 4 pixels ----------------
    const int ob8 = (tid >> 4) * 8;
    const int pb4 = (tid & 15) * 4;

    unsigned long long acc[8][2];
#pragma unroll
    for (int i = 0; i < 8; ++i) { acc[i][0] = 0ull; acc[i][1] = 0ull; }

    // ---------------- prologue: fill buffer 0 -----------------------------
    stage_w(weight, (float4*)wbuf[0], 0, tid);
#pragma unroll
    for (int j = 0; j < 3; ++j) {
        if (j < ntaps) {
            const int i0 = tio[j].x & 0xFFFF, i1 = tio[j].x >> 16;
            const int i2 = tio[j].y & 0xFFFF, i3 = tio[j].y >> 16;
            const float4 w = twt[j];
            float* sd = sbuf[0] + tsb[j];
#pragma unroll
            for (int cl = 0; cl < CHUNK_C; ++cl) {
                const float* q = xp + ((size_t)cl << 12);
                sd[cl * 576] = fmaf(w.x, __ldg(q + i0),
                               fmaf(w.y, __ldg(q + i1),
                               fmaf(w.z, __ldg(q + i2),
                                    w.w * __ldg(q + i3))));
            }
        }
    }
    __syncthreads();

    // ---------------- main loop: stage(i+1) || gemm(i), one sync ---------
    for (int ch = 0; ch < NCHUNK; ++ch) {
        const int cur = ch & 1;

        if (ch + 1 < NCHUNK) {
            const int c0n = (ch + 1) * CHUNK_C;
            stage_w(weight, (float4*)wbuf[cur ^ 1], c0n, tid);
#pragma unroll
            for (int j = 0; j < 3; ++j) {
                if (j < ntaps) {
                    const int i0 = tio[j].x & 0xFFFF, i1 = tio[j].x >> 16;
                    const int i2 = tio[j].y & 0xFFFF, i3 = tio[j].y >> 16;
                    const float4 w = twt[j];
                    const float* pl = xp + ((size_t)c0n << 12);
                    float* sd = sbuf[cur ^ 1] + tsb[j];
#pragma unroll
                    for (int cl = 0; cl < CHUNK_C; ++cl) {
                        const float* q = pl + ((size_t)cl << 12);
                        sd[cl * 576] = fmaf(w.x, __ldg(q + i0),
                                       fmaf(w.y, __ldg(q + i1),
                                       fmaf(w.z, __ldg(q + i2),
                                            w.w * __ldg(q + i3))));
                    }
                }
            }
        }

        // ---- GEMM on current buffers ----
        const float* wc = wbuf[cur];
        const float* sc = sbuf[cur];
#pragma unroll
        for (int k4 = 0; k4 < CHUNK_K / 4; ++k4) {
            const int k = k4 * 4;
            const ulonglong2 s0 = *(const ulonglong2*)(sc + (k + 0) * 64 + pb4);
            const ulonglong2 s1 = *(const ulonglong2*)(sc + (k + 1) * 64 + pb4);
            const ulonglong2 s2 = *(const ulonglong2*)(sc + (k + 2) * 64 + pb4);
            const ulonglong2 s3 = *(const ulonglong2*)(sc + (k + 3) * 64 + pb4);
#pragma unroll
            for (int i = 0; i < 8; ++i) {
                const float4 wv = *(const float4*)(wc + (ob8 + i) * CHUNK_K + k);
                const unsigned long long w0 = pk2(wv.x);
                const unsigned long long w1 = pk2(wv.y);
                const unsigned long long w2 = pk2(wv.z);
                const unsigned long long w3 = pk2(wv.w);
                fma2(acc[i][0], w0, s0.x); fma2(acc[i][1], w0, s0.y);
                fma2(acc[i][0], w1, s1.x); fma2(acc[i][1], w1, s1.y);
                fma2(acc[i][0], w2, s2.x); fma2(acc[i][1], w2, s2.y);
                fma2(acc[i][0], w3, s3.x); fma2(acc[i][1], w3, s3.y);
            }
        }
        __syncthreads();
    }

    // ---------------- epilogue ----------------
#pragma unroll
    for (int i = 0; i < 8; ++i) {
        const int o = ob8 + i;
        const float bi = __ldg(bias + o);
        const float2 v0 = u2f2(acc[i][0]);
        const float2 v1 = u2f2(acc[i][1]);
        float4 r;
        r.x = v0.x + bi;
        r.y = v0.y + bi;
        r.z = v1.x + bi;
        r.w = v1.y + bi;
        float* po = out + (((size_t)bIdx * OO + o) << 12) + (h << 6) + pb4;
        *(float4*)po = r;
    }
}

extern "C" void kernel_launch(void* const* d_in, const int* in_sizes, int n_in,
                              void* d_out, int out_size) {
    const float* x       = (const float*)d_in[0];
    const float* offsets = (const float*)d_in[1];
    const float* mask    = (const float*)d_in[2];
    const float* weight  = (const float*)d_in[3];
    const float* bias    = (const float*)d_in[4];
    float* out = (float*)d_out;

    cudaFuncSetAttribute(dcn_v2_kernel,
                         cudaFuncAttributeMaxDynamicSharedMemorySize, SMEM_BYTES);

    dcn_v2_kernel<<<BB * 64, NTHREADS, SMEM_BYTES>>>(x, offsets, mask, weight, bias, out);
}

// round 7
// speedup vs baseline: 1.0833x; 1.0453x over previous
#include <cuda_runtime.h>
#include <cstdint>

// DCNv2 fused bilinear-sample + implicit GEMM.
// B=8, C=O=128, H=W=64, K=3, pad=dilation=1, dg=1.
// CTA tile: 128 outputs x 128 pixels (2 image rows). grid = 8*32 = 256.
// 256 threads, 8x8 register tile per thread, packed fma.rn.f32x2.
// K-dim (1152) in 16 chunks of 72 (8 channels x 9 taps), double-buffered smem.
// Bilinear taps live in registers (launch_bounds(256,1) -> up to 255 regs).

#define CC 128
#define OO 128
#define CHUNK_C 8
#define CHUNK_K 72
#define NCHUNK 16
#define NPIX 128
#define NTHREADS 256

// smem floats: w[2][128*72]=2*9216, s[2][72*128]=2*9216
#define SMEM_FLOATS (4 * 9216)
#define SMEM_BYTES (SMEM_FLOATS * 4)

__device__ __forceinline__ unsigned long long pk2(float v) {
    unsigned long long r;
    asm("mov.b64 %0, {%1, %1};" : "=l"(r) : "f"(v));
    return r;
}
__device__ __forceinline__ void fma2(unsigned long long& d,
                                     unsigned long long a,
                                     unsigned long long b) {
    asm("fma.rn.f32x2 %0, %1, %2, %0;" : "+l"(d) : "l"(a), "l"(b));
}
__device__ __forceinline__ float2 u2f2(unsigned long long v) {
    float2 f;
    asm("mov.b64 {%0, %1}, %2;" : "=f"(f.x), "=f"(f.y) : "l"(v));
    return f;
}

// Stage weight tile: w_smem[o][0..72) = weight[o][c0*9 .. c0*9+72), o-major.
__device__ __forceinline__ void stage_w(const float* __restrict__ weight,
                                        float4* __restrict__ dst,
                                        int c0, int tid) {
#pragma unroll
    for (int it = 0; it < 9; ++it) {
        const int idx = tid + it * NTHREADS;        // 0..2303
        const int o = idx / 18;
        const int k4 = idx - o * 18;
        dst[idx] = __ldg((const float4*)(weight + (size_t)o * (CC * 9) + c0 * 9) + k4);
    }
}

__global__ void __launch_bounds__(NTHREADS, 1)
dcn_v2_kernel(const float* __restrict__ x,
              const float* __restrict__ offsets,
              const float* __restrict__ mask,
              const float* __restrict__ weight,
              const float* __restrict__ bias,
              float* __restrict__ out) {
    extern __shared__ float smem[];
    float* wbuf[2] = { smem,          smem + 9216 };
    float* sbuf[2] = { smem + 18432,  smem + 27648 };

    const int tid  = threadIdx.x;
    const int bIdx = blockIdx.x >> 5;          // image
    const int h0   = (blockIdx.x & 31) << 1;   // first of 2 rows
    const float* xp = x + ((size_t)bIdx << 19);

    // ------------- register-resident bilinear taps ------------------------
    // 1152 taps = 9 taps x 128 pixels; thread owns e = tid + 256*j.
    // s-tile offset for tap e is exactly e (s layout: [t*128 + pix] per channel*9).
    const int ntaps = 4 + (tid < 128);
    uint2  tio[5];
    float4 twt[5];

#pragma unroll
    for (int j = 0; j < 5; ++j) {
        tio[j] = make_uint2(0u, 0u);
        twt[j] = make_float4(0.f, 0.f, 0.f, 0.f);
        if (j < ntaps) {
            const int e   = tid + (j << 8);
            const int t   = e >> 7;             // 0..8
            const int pix = e & 127;
            const int h   = h0 + (pix >> 6);
            const int wp  = pix & 63;
            const int ky  = t / 3;
            const int kx  = t - ky * 3;
            const int hw  = (h << 6) + wp;

            const size_t ob = ((size_t)bIdx * 18) << 12;
            const float dy = offsets[ob + ((size_t)(2 * t) << 12) + hw];
            const float dx = offsets[ob + ((size_t)(2 * t + 1) << 12) + hw];
            const float m  = mask[(((size_t)bIdx * 9 + t) << 12) + hw];

            const float py = (float)(h - 1 + ky) + dy;
            const float px = (float)(wp - 1 + kx) + dx;
            const float fy = floorf(py);
            const float fx = floorf(px);
            const float ay = py - fy;
            const float ax = px - fx;
            const float by = 1.f - ay;
            const float bx = 1.f - ax;

            const float fy1 = fy + 1.f;
            const float fx1 = fx + 1.f;
            const bool vy0 = (fy  >= 0.f) && (fy  <= 63.f);
            const bool vy1 = (fy1 >= 0.f) && (fy1 <= 63.f);
            const bool vx0 = (fx  >= 0.f) && (fx  <= 63.f);
            const bool vx1 = (fx1 >= 0.f) && (fx1 <= 63.f);

            const int y0 = (int)fminf(fmaxf(fy,  0.f), 63.f);
            const int y1 = (int)fminf(fmaxf(fy1, 0.f), 63.f);
            const int x0 = (int)fminf(fmaxf(fx,  0.f), 63.f);
            const int x1 = (int)fminf(fmaxf(fx1, 0.f), 63.f);

            const unsigned i0 = (unsigned)((y0 << 6) + x0);
            const unsigned i1 = (unsigned)((y0 << 6) + x1);
            const unsigned i2 = (unsigned)((y1 << 6) + x0);
            const unsigned i3 = (unsigned)((y1 << 6) + x1);
            tio[j] = make_uint2(i0 | (i1 << 16), i2 | (i3 << 16));
            twt[j] = make_float4((vy0 && vx0) ? by * bx * m : 0.f,
                                 (vy0 && vx1) ? by * ax * m : 0.f,
                                 (vy1 && vx0) ? ay * bx * m : 0.f,
                                 (vy1 && vx1) ? ay * ax * m : 0.f);
        }
    }

    // ------------- register tile: 8 outputs x 8 pixels --------------------
    const int og8 = (tid >> 4) * 8;       // output base
    const int pb8 = (tid & 15) * 8;       // pixel base (within one row)

    unsigned long long acc[8][4];
#pragma unroll
    for (int i = 0; i < 8; ++i)
#pragma unroll
        for (int q = 0; q < 4; ++q) acc[i][q] = 0ull;

    // ------------- gather-stage helper (inlined twice) --------------------
#define STAGE_S(SDST, C0)                                                     \
    do {                                                                      \
        _Pragma("unroll")                                                     \
        for (int j = 0; j < 5; ++j) {                                         \
            if (j < ntaps) {                                                  \
                const int e = tid + (j << 8);                                 \
                const int i0 = tio[j].x & 0xFFFF, i1 = tio[j].x >> 16;        \
                const int i2 = tio[j].y & 0xFFFF, i3 = tio[j].y >> 16;        \
                const float4 w = twt[j];                                      \
                const float* q0 = xp + ((size_t)(C0) << 12);                  \
                float* sd = (SDST) + e;                                       \
                _Pragma("unroll")                                             \
                for (int cl = 0; cl < CHUNK_C; ++cl) {                        \
                    const float* p = q0 + ((size_t)cl << 12);                 \
                    sd[cl * 1152] = fmaf(w.x, __ldg(p + i0),                  \
                                    fmaf(w.y, __ldg(p + i1),                  \
                                    fmaf(w.z, __ldg(p + i2),                  \
                                         w.w * __ldg(p + i3))));              \
                }                                                             \
            }                                                                 \
        }                                                                     \
    } while (0)

    // ------------- prologue: fill buffer 0 --------------------------------
    stage_w(weight, (float4*)wbuf[0], 0, tid);
    STAGE_S(sbuf[0], 0);
    __syncthreads();

    // ------------- main loop: stage(i+1) || gemm(i), one sync -------------
    for (int ch = 0; ch < NCHUNK; ++ch) {
        const int cur = ch & 1;

        if (ch + 1 < NCHUNK) {
            const int c0n = (ch + 1) * CHUNK_C;
            stage_w(weight, (float4*)wbuf[cur ^ 1], c0n, tid);
            STAGE_S(sbuf[cur ^ 1], c0n);
        }

        const float* wrow = wbuf[cur] + (size_t)og8 * CHUNK_K;
        const float* sc   = sbuf[cur];
#pragma unroll
        for (int k4 = 0; k4 < CHUNK_K / 4; ++k4) {
            float4 wv[8];
#pragma unroll
            for (int i = 0; i < 8; ++i)
                wv[i] = *(const float4*)(wrow + i * CHUNK_K + k4 * 4);
#pragma unroll
            for (int kk = 0; kk < 4; ++kk) {
                const float* srow = sc + (k4 * 4 + kk) * NPIX + pb8;
                const ulonglong2 sA = *(const ulonglong2*)(srow);
                const ulonglong2 sB = *(const ulonglong2*)(srow + 4);
#pragma unroll
                for (int i = 0; i < 8; ++i) {
                    const float wf = (kk == 0) ? wv[i].x :
                                     (kk == 1) ? wv[i].y :
                                     (kk == 2) ? wv[i].z : wv[i].w;
                    const unsigned long long wp = pk2(wf);
                    fma2(acc[i][0], wp, sA.x);
                    fma2(acc[i][1], wp, sA.y);
                    fma2(acc[i][2], wp, sB.x);
                    fma2(acc[i][3], wp, sB.y);
                }
            }
        }
        __syncthreads();
    }

    // ------------- epilogue: + bias, store 2x float4 ----------------------
    const int hh = h0 + (pb8 >> 6);
    const int ww = pb8 & 63;
#pragma unroll
    for (int i = 0; i < 8; ++i) {
        const int o = og8 + i;
        const float bi = __ldg(bias + o);
        const float2 v0 = u2f2(acc[i][0]);
        const float2 v1 = u2f2(acc[i][1]);
        const float2 v2 = u2f2(acc[i][2]);
        const float2 v3 = u2f2(acc[i][3]);
        float4 r0, r1;
        r0.x = v0.x + bi; r0.y = v0.y + bi; r0.z = v1.x + bi; r0.w = v1.y + bi;
        r1.x = v2.x + bi; r1.y = v2.y + bi; r1.z = v3.x + bi; r1.w = v3.y + bi;
        float* po = out + (((size_t)bIdx * OO + o) << 12) + (hh << 6) + ww;
        *(float4*)po = r0;
        *(float4*)(po + 4) = r1;
    }
}

extern "C" void kernel_launch(void* const* d_in, const int* in_sizes, int n_in,
                              void* d_out, int out_size) {
    const float* x       = (const float*)d_in[0];
    const float* offsets = (const float*)d_in[1];
    const float* mask    = (const float*)d_in[2];
    const float* weight  = (const float*)d_in[3];
    const float* bias    = (const float*)d_in[4];
    float* out = (float*)d_out;

    cudaFuncSetAttribute(dcn_v2_kernel,
                         cudaFuncAttributeMaxDynamicSharedMemorySize, SMEM_BYTES);

    dcn_v2_kernel<<<8 * 32, NTHREADS, SMEM_BYTES>>>(x, offsets, mask, weight, bias, out);
}

// round 9
// speedup vs baseline: 1.8128x; 1.6735x over previous
#include <cuda_runtime.h>
#include <cuda_bf16.h>
#include <cstdint>

// DCNv2: fused bilinear gather -> bf16 hi/lo split -> mma.sync.m16n8k16 GEMM.
// B=8, C=O=128, H=W=64, K=3, pad=dilation=1, dg=1.
// CTA: M=128 outputs x N=128 pixels (2 rows), grid=256, 512 threads (16 warps).
// Warp tile m32 x n32. K=1152 in 18 chunks of 64, double-buffered smem tiles.
// 3 MMA passes (hi*hi, hi*lo, lo*hi) accumulate fp32 -> ~fp32 accuracy.

#define NTHREADS 512
#define CHUNK_K 64
#define NCHUNK 18
#define LDT 72                      // padded tile row length (bf16 elems)

// per-buffer tile byte offsets (tiles are 128 x 72 bf16 = 18432 B each)
#define T_WHI 0
#define T_WLO 18432
#define T_SHI 36864
#define T_SLO 55296
#define BUF_BYTES 73728
#define SMEM_BYTES (2 * BUF_BYTES)

#define MMA_BF16(d, a, b)                                                     \
    asm volatile(                                                             \
        "mma.sync.aligned.m16n8k16.row.col.f32.bf16.bf16.f32 "                \
        "{%0,%1,%2,%3}, {%4,%5,%6,%7}, {%8,%9}, {%0,%1,%2,%3};"               \
        : "+f"((d)[0]), "+f"((d)[1]), "+f"((d)[2]), "+f"((d)[3])              \
        : "r"((a)[0]), "r"((a)[1]), "r"((a)[2]), "r"((a)[3]),                 \
          "r"((b)[0]), "r"((b)[1]))

__global__ void __launch_bounds__(NTHREADS, 1)
dcn_v2_kernel(const float* __restrict__ x,
              const float* __restrict__ offsets,
              const float* __restrict__ mask,
              const float* __restrict__ weight,
              const float* __restrict__ bias,
              float* __restrict__ out) {
    extern __shared__ char smem[];

    const int tid  = threadIdx.x;
    const int wid  = tid >> 5;
    const int lane = tid & 31;
    const int grp  = lane >> 2;     // 0..7
    const int qp   = lane & 3;      // 0..3
    const int wm   = wid >> 2;      // warp m-group 0..3
    const int wn   = wid & 3;       // warp n-group 0..3

    const int bIdx = blockIdx.x >> 5;
    const int h0   = (blockIdx.x & 31) << 1;
    const float* xp = x + ((size_t)bIdx << 19);

    // ---- register-resident bilinear taps (1152 = 9 taps x 128 pixels) ----
    const int ntaps = 2 + (tid < 128);
    uint2  tio[3];
    float4 twt[3];
#pragma unroll
    for (int j = 0; j < 3; ++j) {
        tio[j] = make_uint2(0u, 0u);
        twt[j] = make_float4(0.f, 0.f, 0.f, 0.f);
        if (j < ntaps) {
            const int e   = tid + (j << 9);
            const int t   = e >> 7;
            const int pix = e & 127;
            const int h   = h0 + (pix >> 6);
            const int wp  = pix & 63;
            const int ky  = t / 3;
            const int kx  = t - ky * 3;
            const int hw  = (h << 6) + wp;

            const size_t ob = ((size_t)bIdx * 18) << 12;
            const float dy = offsets[ob + ((size_t)(2 * t) << 12) + hw];
            const float dx = offsets[ob + ((size_t)(2 * t + 1) << 12) + hw];
            const float m  = mask[(((size_t)bIdx * 9 + t) << 12) + hw];

            const float py = (float)(h - 1 + ky) + dy;
            const float px = (float)(wp - 1 + kx) + dx;
            const float fy = floorf(py), fx = floorf(px);
            const float ay = py - fy, ax = px - fx;
            const float by = 1.f - ay, bx = 1.f - ax;
            const float fy1 = fy + 1.f, fx1 = fx + 1.f;
            const bool vy0 = (fy  >= 0.f) && (fy  <= 63.f);
            const bool vy1 = (fy1 >= 0.f) && (fy1 <= 63.f);
            const bool vx0 = (fx  >= 0.f) && (fx  <= 63.f);
            const bool vx1 = (fx1 >= 0.f) && (fx1 <= 63.f);
            const int y0 = (int)fminf(fmaxf(fy,  0.f), 63.f);
            const int y1 = (int)fminf(fmaxf(fy1, 0.f), 63.f);
            const int x0 = (int)fminf(fmaxf(fx,  0.f), 63.f);
            const int x1 = (int)fminf(fmaxf(fx1, 0.f), 63.f);
            const unsigned i0 = (unsigned)((y0 << 6) + x0);
            const unsigned i1 = (unsigned)((y0 << 6) + x1);
            const unsigned i2 = (unsigned)((y1 << 6) + x0);
            const unsigned i3 = (unsigned)((y1 << 6) + x1);
            tio[j] = make_uint2(i0 | (i1 << 16), i2 | (i3 << 16));
            twt[j] = make_float4((vy0 && vx0) ? by * bx * m : 0.f,
                                 (vy0 && vx1) ? by * ax * m : 0.f,
                                 (vy1 && vx0) ? ay * bx * m : 0.f,
                                 (vy1 && vx1) ? ay * ax * m : 0.f);
        }
    }

    float acc[2][4][4];
#pragma unroll
    for (int mi = 0; mi < 2; ++mi)
#pragma unroll
        for (int ni = 0; ni < 4; ++ni)
#pragma unroll
            for (int q = 0; q < 4; ++q) acc[mi][ni][q] = 0.f;

    // ---- staging helpers ----
#define STAGE_W(BUF, K0)                                                      \
    do {                                                                      \
        char* dhi = smem + (BUF) * BUF_BYTES + T_WHI;                         \
        char* dlo = smem + (BUF) * BUF_BYTES + T_WLO;                         \
        _Pragma("unroll")                                                     \
        for (int it = 0; it < 4; ++it) {                                      \
            const int idx4 = tid + it * NTHREADS;                             \
            const int o  = idx4 >> 4;                                         \
            const int kq = idx4 & 15;                                         \
            const float4 f = __ldg(                                           \
                (const float4*)(weight + (size_t)o * 1152 + (K0) + kq * 4));  \
            __nv_bfloat162 h01 = __floats2bfloat162_rn(f.x, f.y);             \
            __nv_bfloat162 h23 = __floats2bfloat162_rn(f.z, f.w);             \
            const float2 g01 = __bfloat1622float2(h01);                       \
            const float2 g23 = __bfloat1622float2(h23);                       \
            __nv_bfloat162 l01 = __floats2bfloat162_rn(f.x - g01.x, f.y - g01.y); \
            __nv_bfloat162 l23 = __floats2bfloat162_rn(f.z - g23.x, f.w - g23.y); \
            const int bo = o * (LDT * 2) + kq * 8;                            \
            *(uint2*)(dhi + bo) = make_uint2(*(uint32_t*)&h01, *(uint32_t*)&h23); \
            *(uint2*)(dlo + bo) = make_uint2(*(uint32_t*)&l01, *(uint32_t*)&l23); \
        }                                                                     \
    } while (0)

#define STAGE_S(BUF, K0)                                                      \
    do {                                                                      \
        __nv_bfloat16* dhi = (__nv_bfloat16*)(smem + (BUF) * BUF_BYTES + T_SHI); \
        __nv_bfloat16* dlo = (__nv_bfloat16*)(smem + (BUF) * BUF_BYTES + T_SLO); \
        _Pragma("unroll")                                                     \
        for (int j = 0; j < 3; ++j) {                                         \
            if (j < ntaps) {                                                  \
                const int e   = tid + (j << 9);                               \
                const int t   = e >> 7;                                       \
                const int pix = e & 127;                                      \
                const int i0 = tio[j].x & 0xFFFF, i1 = tio[j].x >> 16;        \
                const int i2 = tio[j].y & 0xFFFF, i3 = tio[j].y >> 16;        \
                const float4 w = twt[j];                                      \
                int c = ((K0) - t + 8) / 9;                                   \
                const int cend = ((K0) + 63 - t) / 9;                         \
                for (; c <= cend; ++c) {                                      \
                    const float* p = xp + ((size_t)c << 12);                  \
                    const float v = fmaf(w.x, __ldg(p + i0),                  \
                                    fmaf(w.y, __ldg(p + i1),                  \
                                    fmaf(w.z, __ldg(p + i2),                  \
                                         w.w * __ldg(p + i3))));              \
                    const __nv_bfloat16 hb = __float2bfloat16(v);             \
                    const __nv_bfloat16 lb =                                  \
                        __float2bfloat16(v - __bfloat162float(hb));           \
                    const int kl = c * 9 + t - (K0);                          \
                    dhi[pix * LDT + kl] = hb;                                 \
                    dlo[pix * LDT + kl] = lb;                                 \
                }                                                             \
            }                                                                 \
        }                                                                     \
    } while (0)

    // ---- prologue ----
    STAGE_W(0, 0);
    STAGE_S(0, 0);
    __syncthreads();

    // ---- main loop: stage(next buffer) overlapped with mma(current) ------
    for (int ch = 0; ch < NCHUNK; ++ch) {
        const int cur = ch & 1;
        if (ch + 1 < NCHUNK) {
            const int k0n = (ch + 1) * CHUNK_K;
            STAGE_W(cur ^ 1, k0n);
            STAGE_S(cur ^ 1, k0n);
        }

        const char* whi = smem + cur * BUF_BYTES + T_WHI;
        const char* wlo = smem + cur * BUF_BYTES + T_WLO;
        const char* shi = smem + cur * BUF_BYTES + T_SHI;
        const char* slo = smem + cur * BUF_BYTES + T_SLO;

#pragma unroll
        for (int ks = 0; ks < 4; ++ks) {
            const int kb = ks * 16 + qp * 2;

            uint32_t ah[2][4], al[2][4];
#pragma unroll
            for (int mi = 0; mi < 2; ++mi) {
                const int r = (wm * 32 + mi * 16 + grp) * LDT + kb;
                ah[mi][0] = *(const uint32_t*)(whi + (size_t)r * 2);
                ah[mi][1] = *(const uint32_t*)(whi + (size_t)(r + 8 * LDT) * 2);
                ah[mi][2] = *(const uint32_t*)(whi + (size_t)(r + 8) * 2);
                ah[mi][3] = *(const uint32_t*)(whi + (size_t)(r + 8 * LDT + 8) * 2);
                al[mi][0] = *(const uint32_t*)(wlo + (size_t)r * 2);
                al[mi][1] = *(const uint32_t*)(wlo + (size_t)(r + 8 * LDT) * 2);
                al[mi][2] = *(const uint32_t*)(wlo + (size_t)(r + 8) * 2);
                al[mi][3] = *(const uint32_t*)(wlo + (size_t)(r + 8 * LDT + 8) * 2);
            }

            uint32_t bh[4][2], bl[4][2];
#pragma unroll
            for (int ni = 0; ni < 4; ++ni) {
                const int r = (wn * 32 + ni * 8 + grp) * LDT + kb;
                bh[ni][0] = *(const uint32_t*)(shi + (size_t)r * 2);
                bh[ni][1] = *(const uint32_t*)(shi + (size_t)(r + 8) * 2);
                bl[ni][0] = *(const uint32_t*)(slo + (size_t)r * 2);
                bl[ni][1] = *(const uint32_t*)(slo + (size_t)(r + 8) * 2);
            }

#pragma unroll
            for (int mi = 0; mi < 2; ++mi)
#pragma unroll
                for (int ni = 0; ni < 4; ++ni) {
                    MMA_BF16(acc[mi][ni], ah[mi], bh[ni]);
                    MMA_BF16(acc[mi][ni], ah[mi], bl[ni]);
                    MMA_BF16(acc[mi][ni], al[mi], bh[ni]);
                }
        }
        __syncthreads();
    }

    // ---- epilogue: + bias, float2 stores -------------------------------
#pragma unroll
    for (int mi = 0; mi < 2; ++mi) {
#pragma unroll
        for (int half = 0; half < 2; ++half) {
            const int o = wm * 32 + mi * 16 + grp + half * 8;
            const float bi = __ldg(bias + o);
            float* po = out + (((size_t)bIdx * 128 + o) << 12) + (h0 << 6);
#pragma unroll
            for (int ni = 0; ni < 4; ++ni) {
                const int n = wn * 32 + ni * 8 + qp * 2;
                float2 v;
                v.x = acc[mi][ni][half * 2 + 0] + bi;
                v.y = acc[mi][ni][half * 2 + 1] + bi;
                *(float2*)(po + n) = v;
            }
        }
    }
}

extern "C" void kernel_launch(void* const* d_in, const int* in_sizes, int n_in,
                              void* d_out, int out_size) {
    const float* x       = (const float*)d_in[0];
    const float* offsets = (const float*)d_in[1];
    const float* mask    = (const float*)d_in[2];
    const float* weight  = (const float*)d_in[3];
    const float* bias    = (const float*)d_in[4];
    float* out = (float*)d_out;

    cudaFuncSetAttribute(dcn_v2_kernel,
                         cudaFuncAttributeMaxDynamicSharedMemorySize, SMEM_BYTES);

    dcn_v2_kernel<<<256, NTHREADS, SMEM_BYTES>>>(x, offsets, mask, weight, bias, out);
}